// round 12
// baseline (speedup 1.0000x reference)
#include <cuda_runtime.h>
#include <cuda_bf16.h>

// NDFT type-2, conjugate-pair symmetry over k1 (f_hat real):
//   pair +-t: f[t]e^{-ip} + f[-t]e^{+ip} = fs*cos(p) - i*fd*sin(p)
//   t=0 (k1=0): fs=f, fd=-f (killed by sin(0)=0); t=32 (k1=-32): fs=f, fd=-f;
//   t=33: zero pad. Radix on k2: k2 = 16a + c - 32.
// Kernel 1 (prep): build interleaved (fs,fd) into a __device__ global once.
// Kernel 2 (main): per block copy 17KB to smem, 8 warps = (a, t-half),
//   lane = (point p, c-half ch): acc[j]=(P,Q) packed, 1 fma.rn.f32x2/c/row.
// Tail: y_p = C_a * sum_j w2^{8ch+j}(P-iQ); 16 partials/point via smem.
// Twiddles via MUFU __sincosf.

#define B_DIM 2
#define M_DIM 8192
#define N1 64
#define N2 64
#define K_TOT (N1 * N2)
#define TPB 256
#define NWARP 8
#define PTS 16
#define BLOCKS_PER_B (M_DIM / PTS)           // 512
#define TROWS 34                             // t = 0..32 + zero pad row 33
#define ROWS_PW 17

#define PI_F     3.14159265358979f
#define TWO_PI_F 6.28318530717959f

typedef unsigned long long ull;

#define PACK2(d, lo, hi) \
    asm("mov.b64 %0, {%1, %2};" : "=l"(d) \
        : "r"(__float_as_uint(lo)), "r"(__float_as_uint(hi)))
#define FMA2(d, a, b, c) \
    asm("fma.rn.f32x2 %0, %1, %2, %3;" : "=l"(d) : "l"(a), "l"(b), "l"(c))
#define UNPACK2(lo, hi, s) do { unsigned int _l, _h; \
    asm("mov.b64 {%0, %1}, %2;" : "=r"(_l), "=r"(_h) : "l"(s)); \
    (lo) = __uint_as_float(_l); (hi) = __uint_as_float(_h); } while (0)

// one-time (fs,fd) interleaved table: [B][t][a*32 + c*2]
__device__ __align__(16) float gfsd[B_DIM * TROWS * 128];

__global__ __launch_bounds__(256) void prep_kernel(
    const float* __restrict__ f_hat)   // [B, 64, 64]
{
    const int b = blockIdx.x;
    const float* fb = f_hat + b * K_TOT;
    float* gout = gfsd + b * TROWS * 128;

    for (int idx = threadIdx.x; idx < TROWS * 16; idx += 256) {
        const int t = idx >> 4;
        const int g = idx & 15;
        float4 fp = make_float4(0.f, 0.f, 0.f, 0.f);
        float4 fm = make_float4(0.f, 0.f, 0.f, 0.f);
        if (t >= 1 && t <= 31)
            fp = *reinterpret_cast<const float4*>(fb + (32 + t) * N2 + g * 4);
        if (t <= 32)
            fm = *reinterpret_cast<const float4*>(fb + (32 - t) * N2 + g * 4);
        float4* dst = reinterpret_cast<float4*>(gout + t * 128 + g * 8);
        dst[0] = make_float4(fp.x + fm.x, fp.x - fm.x, fp.y + fm.y, fp.y - fm.y);
        dst[1] = make_float4(fp.z + fm.z, fp.z - fm.z, fp.w + fm.w, fp.w - fm.w);
    }
}

__global__ __launch_bounds__(TPB, 6) void ndft_kernel(
    const float* __restrict__ x,      // [B, M, 2]
    float* __restrict__ out,
    const int real_only)
{
    __shared__ __align__(16) float sfd[TROWS * 128];  // (fs,fd) interleaved
    __shared__ float2 sy[NWARP * 2][PTS];             // 16 partials per point

    const int b    = blockIdx.x / BLOCKS_PER_B;
    const int mblk = blockIdx.x % BLOCKS_PER_B;
    const int tid  = threadIdx.x;
    const int w    = tid >> 5;
    const int lane = tid & 31;
    const int a    = w & 3;                  // k2 radix digit
    const int h    = w >> 2;                 // t-half
    const int p    = lane & 15;              // point within block
    const int ch   = lane >> 4;              // c-half: c = 8*ch + j
    const int m    = mblk * PTS + p;

    // ---- copy prebuilt (fs,fd) table into smem (pure float4 stream) ----
    {
        const float4* src = reinterpret_cast<const float4*>(gfsd + b * TROWS * 128);
        float4* dst = reinterpret_cast<float4*>(sfd);
        #pragma unroll
        for (int i = tid; i < TROWS * 32; i += TPB)   // 1088 float4
            dst[i] = src[i];
    }

    const float2 xv = reinterpret_cast<const float2*>(x)[b * M_DIM + m];
    const float x1 = xv.x, x2 = xv.y;
    __syncthreads();

    // ---- twiddles via MUFU (__sincosf), radians ----
    float rc, rs;                      // rotation cis(+2*pi*x1) per t step
    __sincosf(TWO_PI_F * x1, &rs, &rc);
    float ct, st;                      // anchor cis(2*pi*17h*x1)
    if (h == 0) { ct = 1.0f; st = 0.0f; }
    else        __sincosf(TWO_PI_F * 17.0f * x1, &st, &ct);
    float w2r, w2i;                    // w2 = cis(-2*pi*x2)
    __sincosf(-TWO_PI_F * x2, &w2i, &w2r);
    float Cr, Ci;                      // C_a = cis(-2*pi*(16a-32)*x2)
    __sincosf((64.0f - 32.0f * (float)a) * PI_F * x2, &Ci, &Cr);
    float f0r, f0i;                    // E2f anchor = cis(-2*pi*8*ch*x2)
    if (ch == 0) { f0r = 1.0f; f0i = 0.0f; }
    else        __sincosf(-16.0f * PI_F * x2, &f0i, &f0r);

    // packed accumulators: acc[j] = (P, Q) for local c = 8*ch + j
    ull acc[8];
    #pragma unroll
    for (int j = 0; j < 8; ++j) acc[j] = 0ull;

    // this lane's slice: 4 x 16B per row, at a*128B + ch*64B
    const ulonglong2* fsd = reinterpret_cast<const ulonglong2*>(
        sfd + (h * ROWS_PW) * 128 + a * 32 + ch * 16);

    #pragma unroll
    for (int t = 0; t < ROWS_PW; ++t) {
        ull cs;
        PACK2(cs, ct, st);             // (cos_t, sin_t)

        const ulonglong2 v0 = fsd[0];  // (fs,fd) pairs c = 8ch+0..3
        const ulonglong2 v1 = fsd[1];
        const ulonglong2 v2 = fsd[2];  // c = 8ch+4..7
        const ulonglong2 v3 = fsd[3];

        // rotate cis early (independent of the FMA block below)
        const float nc = ct * rc - st * rs;
        st = ct * rs + st * rc;
        ct = nc;

        FMA2(acc[0], v0.x, cs, acc[0]);
        FMA2(acc[1], v0.y, cs, acc[1]);
        FMA2(acc[2], v1.x, cs, acc[2]);
        FMA2(acc[3], v1.y, cs, acc[3]);
        FMA2(acc[4], v2.x, cs, acc[4]);
        FMA2(acc[5], v2.y, cs, acc[5]);
        FMA2(acc[6], v3.x, cs, acc[6]);
        FMA2(acc[7], v3.y, cs, acc[7]);

        fsd += 128 / 4;                // next t row (128 floats)
    }

    // ---- tail: T = sum_j w2^{8ch+j} (P_j - i Q_j);  y = C_a * T ----
    float Tr = 0.0f, Ti = 0.0f;
    {
        float fr = f0r, fi = f0i;
        #pragma unroll
        for (int j = 0; j < 8; ++j) {
            float P, Q;
            UNPACK2(P, Q, acc[j]);
            Tr += fr * P + fi * Q;
            Ti += fi * P - fr * Q;
            const float tt = fr * w2r - fi * w2i;
            fi = fr * w2i + fi * w2r;
            fr = tt;
        }
    }
    const float yr = Cr * Tr - Ci * Ti;
    const float yi = Cr * Ti + Ci * Tr;

    // ---- reduction: 16 partials per point ----
    sy[w * 2 + ch][p] = make_float2(yr, yi);
    __syncthreads();

    if (tid < PTS) {
        float2 s = sy[0][tid];
        #pragma unroll
        for (int q = 1; q < NWARP * 2; ++q) {
            s.x += sy[q][tid].x;
            s.y += sy[q][tid].y;
        }
        const int mo = b * M_DIM + mblk * PTS + tid;
        if (real_only) {
            out[mo] = s.x;
        } else {
            reinterpret_cast<float2*>(out)[mo] = s;
        }
    }
}

extern "C" void kernel_launch(void* const* d_in, const int* in_sizes, int n_in,
                              void* d_out, int out_size) {
    // Select inputs by element count (metadata order may differ):
    //   x: 2*8192*2 = 32768, f_hat: 2*64*64 = 8192
    const float* x;
    const float* f_hat;
    if (in_sizes[0] == B_DIM * M_DIM * 2) {
        x = (const float*)d_in[0];
        f_hat = (const float*)d_in[1];
    } else {
        x = (const float*)d_in[1];
        f_hat = (const float*)d_in[0];
    }

    float* out = (float*)d_out;
    const int real_only = (out_size == B_DIM * M_DIM) ? 1 : 0;

    prep_kernel<<<B_DIM, 256>>>(f_hat);
    ndft_kernel<<<B_DIM * BLOCKS_PER_B, TPB>>>(x, out, real_only);
}

// round 13
// speedup vs baseline: 1.3791x; 1.3791x over previous
#include <cuda_runtime.h>
#include <cuda_bf16.h>

// NDFT type-2, conjugate-pair symmetry over k1 (f_hat real):
//   pair +-t: f[t]e^{-ip} + f[-t]e^{+ip} = fs*cos(p) - i*fd*sin(p)
//   t=0 (k1=0): fs=f, fd=-f (killed by sin(0)=0); t=32 (k1=-32): fs=f, fd=-f;
//   t=33: zero pad. Radix on k2: k2 = 16a + c - 32.
// Block: 128 thr = 4 warps, 16 points. warp = a (k2 radix digit), covers ALL
// 34 t-rows (fat warps amortize per-warp fixed overhead).
// lane = (point p = lane&15, c-half ch = lane>>4): 8 c's per lane,
//   acc[j] = (P,Q) packed, ONE fma.rn.f32x2 per c per row.
// Tail: y_p = C_a * sum_j w2^{8ch+j}(P-iQ); 8 partials/point via smem.
// Twiddles via MUFU __sincosf.

#define B_DIM 2
#define M_DIM 8192
#define N1 64
#define N2 64
#define K_TOT (N1 * N2)
#define TPB 128
#define NWARP 4
#define PTS 16
#define BLOCKS_PER_B (M_DIM / PTS)           // 512
#define TROWS 34                             // t = 0..32 + zero pad row 33

#define PI_F     3.14159265358979f
#define TWO_PI_F 6.28318530717959f

typedef unsigned long long ull;

#define PACK2(d, lo, hi) \
    asm("mov.b64 %0, {%1, %2};" : "=l"(d) \
        : "r"(__float_as_uint(lo)), "r"(__float_as_uint(hi)))
#define FMA2(d, a, b, c) \
    asm("fma.rn.f32x2 %0, %1, %2, %3;" : "=l"(d) : "l"(a), "l"(b), "l"(c))
#define UNPACK2(lo, hi, s) do { unsigned int _l, _h; \
    asm("mov.b64 {%0, %1}, %2;" : "=r"(_l), "=r"(_h) : "l"(s)); \
    (lo) = __uint_as_float(_l); (hi) = __uint_as_float(_h); } while (0)

__global__ __launch_bounds__(TPB, 8) void ndft_kernel(
    const float* __restrict__ x,      // [B, M, 2]
    const float* __restrict__ f_hat,  // [B, 64, 64]
    float* __restrict__ out,
    const int real_only)
{
    __shared__ __align__(16) float sfd[TROWS * 128];  // (fs,fd) interleaved
    __shared__ float2 sy[NWARP * 2][PTS];             // 8 partials per point

    const int b    = blockIdx.x / BLOCKS_PER_B;
    const int mblk = blockIdx.x % BLOCKS_PER_B;
    const int tid  = threadIdx.x;
    const int w    = tid >> 5;               // warp id = a (k2 radix digit)
    const int lane = tid & 31;
    const int p    = lane & 15;              // point within block
    const int ch   = lane >> 4;              // c-half: c = 8*ch + j
    const int m    = mblk * PTS + p;

    // ---- build fs/fd interleaved: sfd[t*128 + a*32 + c*2] = (fs, fd) ----
    {
        const float* fb = f_hat + b * K_TOT;
        for (int idx = tid; idx < TROWS * 16; idx += TPB) {
            const int t = idx >> 4;
            const int g = idx & 15;
            float4 fp = make_float4(0.f, 0.f, 0.f, 0.f);
            float4 fm = make_float4(0.f, 0.f, 0.f, 0.f);
            if (t >= 1 && t <= 31)
                fp = *reinterpret_cast<const float4*>(fb + (32 + t) * N2 + g * 4);
            if (t <= 32)
                fm = *reinterpret_cast<const float4*>(fb + (32 - t) * N2 + g * 4);
            float4* dst = reinterpret_cast<float4*>(sfd + t * 128 + g * 8);
            dst[0] = make_float4(fp.x + fm.x, fp.x - fm.x, fp.y + fm.y, fp.y - fm.y);
            dst[1] = make_float4(fp.z + fm.z, fp.z - fm.z, fp.w + fm.w, fp.w - fm.w);
        }
    }

    const float2 xv = reinterpret_cast<const float2*>(x)[b * M_DIM + m];
    const float x1 = xv.x, x2 = xv.y;
    __syncthreads();

    // ---- twiddles via MUFU (__sincosf), radians ----
    float rc, rs;                      // rotation cis(+2*pi*x1) per t step
    __sincosf(TWO_PI_F * x1, &rs, &rc);
    float ct = 1.0f, st = 0.0f;        // anchor cis(0) (t starts at 0)
    float w2r, w2i;                    // w2 = cis(-2*pi*x2)
    __sincosf(-TWO_PI_F * x2, &w2i, &w2r);
    float Cr, Ci;                      // C_a = cis(-2*pi*(16a-32)*x2)
    __sincosf((64.0f - 32.0f * (float)w) * PI_F * x2, &Ci, &Cr);
    float f0r, f0i;                    // E2f anchor = cis(-2*pi*8*ch*x2)
    if (ch == 0) { f0r = 1.0f; f0i = 0.0f; }
    else        __sincosf(-16.0f * PI_F * x2, &f0i, &f0r);

    // packed accumulators: acc[j] = (P, Q) for local c = 8*ch + j
    ull acc[8];
    #pragma unroll
    for (int j = 0; j < 8; ++j) acc[j] = 0ull;

    // this lane's slice: 4 x 16B per row, at a*128B + ch*64B
    const ulonglong2* fsd = reinterpret_cast<const ulonglong2*>(
        sfd + w * 32 + ch * 16);

    #pragma unroll 2
    for (int t = 0; t < TROWS; ++t) {
        ull cs;
        PACK2(cs, ct, st);             // (cos_t, sin_t)

        const ulonglong2 v0 = fsd[0];  // (fs,fd) pairs c = 8ch+0..3
        const ulonglong2 v1 = fsd[1];
        const ulonglong2 v2 = fsd[2];  // c = 8ch+4..7
        const ulonglong2 v3 = fsd[3];

        // rotate cis early (independent of the FMA block below)
        const float nc = ct * rc - st * rs;
        st = ct * rs + st * rc;
        ct = nc;

        FMA2(acc[0], v0.x, cs, acc[0]);
        FMA2(acc[1], v0.y, cs, acc[1]);
        FMA2(acc[2], v1.x, cs, acc[2]);
        FMA2(acc[3], v1.y, cs, acc[3]);
        FMA2(acc[4], v2.x, cs, acc[4]);
        FMA2(acc[5], v2.y, cs, acc[5]);
        FMA2(acc[6], v3.x, cs, acc[6]);
        FMA2(acc[7], v3.y, cs, acc[7]);

        fsd += 128 / 4;                // next t row (128 floats)
    }

    // ---- tail: T = sum_j w2^{8ch+j} (P_j - i Q_j);  y = C_a * T ----
    float Tr = 0.0f, Ti = 0.0f;
    {
        float fr = f0r, fi = f0i;
        #pragma unroll
        for (int j = 0; j < 8; ++j) {
            float P, Q;
            UNPACK2(P, Q, acc[j]);
            Tr += fr * P + fi * Q;
            Ti += fi * P - fr * Q;
            const float tt = fr * w2r - fi * w2i;
            fi = fr * w2i + fi * w2r;
            fr = tt;
        }
    }
    const float yr = Cr * Tr - Ci * Ti;
    const float yi = Cr * Ti + Ci * Tr;

    // ---- reduction: 8 partials per point ----
    sy[w * 2 + ch][p] = make_float2(yr, yi);
    __syncthreads();

    if (tid < PTS) {
        float2 s = sy[0][tid];
        #pragma unroll
        for (int q = 1; q < NWARP * 2; ++q) {
            s.x += sy[q][tid].x;
            s.y += sy[q][tid].y;
        }
        const int mo = b * M_DIM + mblk * PTS + tid;
        if (real_only) {
            out[mo] = s.x;
        } else {
            reinterpret_cast<float2*>(out)[mo] = s;
        }
    }
}

extern "C" void kernel_launch(void* const* d_in, const int* in_sizes, int n_in,
                              void* d_out, int out_size) {
    // Select inputs by element count (metadata order may differ):
    //   x: 2*8192*2 = 32768, f_hat: 2*64*64 = 8192
    const float* x;
    const float* f_hat;
    if (in_sizes[0] == B_DIM * M_DIM * 2) {
        x = (const float*)d_in[0];
        f_hat = (const float*)d_in[1];
    } else {
        x = (const float*)d_in[1];
        f_hat = (const float*)d_in[0];
    }

    float* out = (float*)d_out;
    const int real_only = (out_size == B_DIM * M_DIM) ? 1 : 0;

    ndft_kernel<<<B_DIM * BLOCKS_PER_B, TPB>>>(x, f_hat, out, real_only);
}